// round 8
// baseline (speedup 1.0000x reference)
#include <cuda_runtime.h>
#include <math.h>
#include <stdint.h>

#define EPS  1e-5f
#define HHH  192
// smem layout (float offsets)
#define CPO  0                       // params: up to 6 x 64 floats
#define AO   384                     // A tile: 128 rows x 36 float4 (hi,lo,hi4,lo4)
#define WO   (AO + 128 * 36 * 4)     // 18816: W tile 32 x 66 float4 / ys 128 x 68 floats
#define SMF  (WO + 8704)             // 27520 floats
#define SMB  (SMF * 4)               // 110080 bytes

// Scratch (device globals — allocation-free)
__device__ __align__(16) float g_S[32 * 64 * 64 * 64];        // 3x3 sub-block sums
__device__ __align__(16) float g_tok[2 * 32 * 32 * 32 * 64];  // tokens [p][b][i][j][c]

__device__ __forceinline__ float tf32r(float x) {
    uint32_t u; asm("cvt.rna.tf32.f32 %0, %1;" : "=r"(u) : "f"(x));
    return __uint_as_float(u);
}
__device__ __forceinline__ float2 split2(float x) {
    float h = tf32r(x);
    return make_float2(h, tf32r(x - h));
}
__device__ __forceinline__ void mma8(float* d, const uint32_t* a, uint32_t b0, uint32_t b1) {
    asm volatile(
        "mma.sync.aligned.m16n8k8.row.col.f32.tf32.tf32.f32 "
        "{%0,%1,%2,%3}, {%4,%5,%6,%7}, {%8,%9}, {%0,%1,%2,%3};"
        : "+f"(d[0]), "+f"(d[1]), "+f"(d[2]), "+f"(d[3])
        : "r"(a[0]), "r"(a[1]), "r"(a[2]), "r"(a[3]), "r"(b0), "r"(b1));
}
__device__ __forceinline__ float gelu_exact(float v) {
    return 0.5f * v * (1.0f + erff(v * 0.7071067811865476f));
}
#define FU(x) __float_as_uint(x)

// ---------------------------------------------------------------------------
// K1: 3x3 sub-block sums (83% of DRAM roofline — unchanged).
// ---------------------------------------------------------------------------
__global__ void __launch_bounds__(256) k1_subsum(const float* __restrict__ x) {
    int tid = blockIdx.x * blockDim.x + threadIdx.x;
    int c4 = tid & 15;
    int sw = (tid >> 4) & 63;
    int sh = (tid >> 10) & 63;
    int b  = tid >> 16;
    const float4* x4 = (const float4*)x;
    float4 acc = make_float4(0.f, 0.f, 0.f, 0.f);
    int rowbase = (b * HHH + sh * 3) * HHH + sw * 3;
#pragma unroll
    for (int dh = 0; dh < 3; dh++)
#pragma unroll
        for (int dw = 0; dw < 3; dw++) {
            float4 v = x4[(rowbase + dh * HHH + dw) * 16 + c4];
            acc.x += v.x; acc.y += v.y; acc.z += v.z; acc.w += v.w;
        }
    ((float4*)g_S)[tid] = acc;
}

// W[k][n] (64x64) -> packed tiles: wp[(k>>3)*4 + (k&3)][n] float4,
// halves: (k>>2)&1 selects (.x,.y) vs (.z,.w) = (hi,lo).
__device__ __forceinline__ void load_wsplit(const float* __restrict__ W, float* sm, int tid) {
    float4* wp = (float4*)(sm + WO);
#pragma unroll
    for (int e = 0; e < 4; e++) {
        int idx = e * 256 + tid;
        int k = idx >> 4, n4 = idx & 15;
        float4 wv = ((const float4*)W)[idx];
        int sq = (k >> 3) * 4 + (k & 3);
        int half = (k >> 2) & 1;
        float* base = (float*)(wp + sq * 66 + 4 * n4) + 2 * half;
        *(float2*)(base)      = split2(wv.x);
        *(float2*)(base + 4)  = split2(wv.y);
        *(float2*)(base + 8)  = split2(wv.z);
        *(float2*)(base + 12) = split2(wv.w);
    }
}

// store 4 consecutive k-values (k = 4*c4 + j) of row r into packed A tile
__device__ __forceinline__ void store_a4(float* sm, int r, int c4, float4 xv) {
    float4* af4 = (float4*)(sm + AO);
    int half = c4 & 1;
    float4* slot = af4 + r * 36 + (c4 >> 1) * 4;
    *((float2*)(slot + 0) + half) = split2(xv.x);
    *((float2*)(slot + 1) + half) = split2(xv.y);
    *((float2*)(slot + 2) + half) = split2(xv.z);
    *((float2*)(slot + 3) + half) = split2(xv.w);
}

// GEMM(128x64 @ 64x64), tf32 3-pass split (pass-major ordering) + bias+LN+GELU.
// Warp w rows [16w,16w+16): v[0]=row 16w+g, v[1]=row 16w+8+g; cols 8j+2q+{0,1}.
__device__ __forceinline__ void gemm_ln_gelu(const float* sm, const float* cp, int tid,
                                             float v[2][16]) {
    const float4* af4 = (const float4*)(sm + AO);
    const float4* wp  = (const float4*)(sm + WO);
    int w = tid >> 5, lane = tid & 31, g = lane >> 2, q = lane & 3;
    float acc[8][4];
#pragma unroll
    for (int j = 0; j < 8; j++) {
        float2 b2 = *(const float2*)(cp + 8 * j + 2 * q);
        acc[j][0] = b2.x; acc[j][1] = b2.y; acc[j][2] = b2.x; acc[j][3] = b2.y;
    }
    int r0 = 16 * w + g;
    const float4* a0p = af4 + r0 * 36 + q;
    const float4* a1p = af4 + (r0 + 8) * 36 + q;
#pragma unroll
    for (int ks = 0; ks < 8; ks++) {
        float4 a0 = a0p[ks * 4];
        float4 a1 = a1p[ks * 4];
        uint32_t Ahi[4] = { FU(a0.x), FU(a1.x), FU(a0.z), FU(a1.z) };
        uint32_t Alo[4] = { FU(a0.y), FU(a1.y), FU(a0.w), FU(a1.w) };
        const float4* wrow = wp + (ks * 4 + q) * 66 + g;
        float4 wv[8];
#pragma unroll
        for (int j = 0; j < 8; j++) wv[j] = wrow[8 * j];
#pragma unroll
        for (int j = 0; j < 8; j++) mma8(acc[j], Ahi, FU(wv[j].x), FU(wv[j].z));
#pragma unroll
        for (int j = 0; j < 8; j++) mma8(acc[j], Ahi, FU(wv[j].y), FU(wv[j].w));
#pragma unroll
        for (int j = 0; j < 8; j++) mma8(acc[j], Alo, FU(wv[j].x), FU(wv[j].z));
    }
#pragma unroll
    for (int j = 0; j < 8; j++) {
        v[0][2 * j] = acc[j][0]; v[0][2 * j + 1] = acc[j][1];
        v[1][2 * j] = acc[j][2]; v[1][2 * j + 1] = acc[j][3];
    }
#pragma unroll
    for (int t = 0; t < 2; t++) {
        float s = 0.f;
#pragma unroll
        for (int i = 0; i < 16; i++) s += v[t][i];
        s += __shfl_xor_sync(0xffffffffu, s, 1);
        s += __shfl_xor_sync(0xffffffffu, s, 2);
        float mean = s * (1.0f / 64.0f);
        float var = 0.f;
#pragma unroll
        for (int i = 0; i < 16; i++) { float d = v[t][i] - mean; var += d * d; }
        var += __shfl_xor_sync(0xffffffffu, var, 1);
        var += __shfl_xor_sync(0xffffffffu, var, 2);
        float rstd = rsqrtf(var * (1.0f / 64.0f) + EPS);
#pragma unroll
        for (int j = 0; j < 8; j++) {
            float2 gm = *(const float2*)(cp + 64  + 8 * j + 2 * q);
            float2 bt = *(const float2*)(cp + 128 + 8 * j + 2 * q);
            v[t][2 * j]     = gelu_exact((v[t][2 * j]     - mean) * rstd * gm.x + bt.x);
            v[t][2 * j + 1] = gelu_exact((v[t][2 * j + 1] - mean) * rstd * gm.y + bt.y);
        }
    }
}

// ---------------------------------------------------------------------------
// K2: token projection (both paths). 128 rows/CTA, 512 CTAs.
// ---------------------------------------------------------------------------
__global__ void __launch_bounds__(256) k2_token(
    const float* __restrict__ tW, const float* __restrict__ tb,
    const float* __restrict__ tg, const float* __restrict__ tbe)
{
    extern __shared__ __align__(16) float sm[];
    int tid = threadIdx.x;
    if (tid < 64) {
        sm[CPO + tid] = tb[tid]; sm[CPO + 64 + tid] = tg[tid]; sm[CPO + 128 + tid] = tbe[tid];
    }
    load_wsplit(tW, sm, tid);
    int R0 = blockIdx.x * 128;
#pragma unroll 2
    for (int e = 0; e < 8; e++) {
        int idx = e * 256 + tid;
        int r = idx >> 4, c4 = idx & 15;
        int R = R0 + r;
        int p = R >> 15, rem = R & 32767;
        int bb = rem >> 10, ii = (rem >> 5) & 31, jj = rem & 31;
        int r0, r1, q0, q1;
        if (p == 0) { r0 = 2 * ii;            r1 = 2 * ii + 1;
                      q0 = 2 * jj;            q1 = 2 * jj + 1; }
        else        { r0 = (2 * ii + 1) & 63; r1 = (2 * ii + 2) & 63;
                      q0 = (2 * jj + 1) & 63; q1 = (2 * jj + 2) & 63; }
        const float4* Sb = (const float4*)g_S + bb * 65536;
        float4 s0 = Sb[(r0 * 64 + q0) * 16 + c4];
        float4 s1 = Sb[(r0 * 64 + q1) * 16 + c4];
        float4 s2 = Sb[(r1 * 64 + q0) * 16 + c4];
        float4 s3 = Sb[(r1 * 64 + q1) * 16 + c4];
        store_a4(sm, r, c4,
            make_float4((s0.x + s1.x + s2.x + s3.x) * (1.0f / 36.0f),
                        (s0.y + s1.y + s2.y + s3.y) * (1.0f / 36.0f),
                        (s0.z + s1.z + s2.z + s3.z) * (1.0f / 36.0f),
                        (s0.w + s1.w + s2.w + s3.w) * (1.0f / 36.0f)));
    }
    __syncthreads();
    float v[2][16];
    gemm_ln_gelu(sm, sm + CPO, tid, v);
    int w = tid >> 5, lane = tid & 31, g = lane >> 2, q = lane & 3;
    int R = R0 + 16 * w + g;
#pragma unroll
    for (int j = 0; j < 8; j++) {
        *(float2*)&g_tok[R * 64 + 8 * j + 2 * q]       = make_float2(v[0][2*j], v[0][2*j+1]);
        *(float2*)&g_tok[(R + 8) * 64 + 8 * j + 2 * q] = make_float2(v[1][2*j], v[1][2*j+1]);
    }
}

// ---------------------------------------------------------------------------
// K3: fuse + out layers per unique 3x3 block (128 rows/CTA, 1024 CTAs),
// broadcast each row to its 9 output pixels.
// ---------------------------------------------------------------------------
__global__ void __launch_bounds__(256) k3_fuse_out(
    const float* __restrict__ fW, const float* __restrict__ fb,
    const float* __restrict__ fg, const float* __restrict__ fbe,
    const float* __restrict__ oW, const float* __restrict__ ob,
    const float* __restrict__ og, const float* __restrict__ obe,
    float* __restrict__ out)
{
    extern __shared__ __align__(16) float sm[];
    int tid = threadIdx.x;
    if (tid < 64) {
        sm[CPO + tid]       = fb[tid]; sm[CPO + 64 + tid]  = fg[tid]; sm[CPO + 128 + tid] = fbe[tid];
        sm[CPO + 192 + tid] = ob[tid]; sm[CPO + 256 + tid] = og[tid]; sm[CPO + 320 + tid] = obe[tid];
    }
    load_wsplit(fW, sm, tid);
    int R0 = blockIdx.x * 128;
#pragma unroll 2
    for (int e = 0; e < 8; e++) {
        int idx = e * 256 + tid;
        int r = idx >> 4, c4 = idx & 15;
        int R = R0 + r;
        int bb = R >> 12, qh = (R >> 6) & 63, qw = R & 63;
        int ih = qh >> 1, iw = qw >> 1;
        int sh = ((qh + 63) & 63) >> 1, sw_ = ((qw + 63) & 63) >> 1;
        float4 a = ((const float4*)g_tok)[((bb * 32 + ih) * 32 + iw) * 16 + c4];
        float4 s = ((const float4*)g_tok)[524288 + ((bb * 32 + sh) * 32 + sw_) * 16 + c4];
        store_a4(sm, r, c4, make_float4(a.x + s.x, a.y + s.y, a.z + s.z, a.w + s.w));
    }
    __syncthreads();
    int w = tid >> 5, lane = tid & 31, g = lane >> 2, q = lane & 3;
    int r0 = 16 * w + g;
    float v[2][16];
    // ---- layer 1: fuse ----
    gemm_ln_gelu(sm, sm + CPO, tid, v);
    __syncthreads();                       // all A/W reads done
    // writeback split activations into A tile; reload W with out_W
    {
        float4* af4 = (float4*)(sm + AO);
#pragma unroll
        for (int t = 0; t < 2; t++) {
            int r = r0 + 8 * t;
#pragma unroll
            for (int j = 0; j < 8; j++) {
#pragma unroll
                for (int d = 0; d < 2; d++) {
                    int c = 8 * j + 2 * q + d;
                    float4* slot = af4 + r * 36 + (c >> 3) * 4 + (c & 3);
                    *((float2*)slot + ((c >> 2) & 1)) = split2(v[t][2 * j + d]);
                }
            }
        }
    }
    load_wsplit(oW, sm, tid);
    __syncthreads();
    // ---- layer 2: out ----
    gemm_ln_gelu(sm, sm + CPO + 192, tid, v);
    __syncthreads();                       // all W reads done; reuse W region as ys
    float* ys = sm + WO;                   // 128 rows x stride 68
#pragma unroll
    for (int t = 0; t < 2; t++) {
        int r = r0 + 8 * t;
#pragma unroll
        for (int j = 0; j < 8; j++)
            *(float2*)&ys[r * 68 + 8 * j + 2 * q] = make_float2(v[t][2*j], v[t][2*j+1]);
    }
    __syncthreads();
    // coalesced 3x3 broadcast
    float4* o4 = (float4*)out;
#pragma unroll 2
    for (int e = 0; e < 8; e++) {
        int idx = e * 256 + tid;
        int r = idx >> 4, c4 = idx & 15;
        float4 val = *(float4*)(ys + r * 68 + 4 * c4);
        int R = R0 + r;
        int bb = R >> 12, qh = (R >> 6) & 63, qw = R & 63;
        int base = (bb * 36864 + qh * 3 * HHH + qw * 3) * 16 + c4;
#pragma unroll
        for (int dh = 0; dh < 3; dh++)
#pragma unroll
            for (int dw = 0; dw < 3; dw++)
                o4[base + (dh * HHH + dw) * 16] = val;
    }
}

// ---------------------------------------------------------------------------
extern "C" void kernel_launch(void* const* d_in, const int* in_sizes, int n_in,
                              void* d_out, int out_size) {
    const float* h_pixel = (const float*)d_in[0];
    const float* tW  = (const float*)d_in[1];
    const float* tb  = (const float*)d_in[2];
    const float* tg  = (const float*)d_in[3];
    const float* tbe = (const float*)d_in[4];
    const float* fW  = (const float*)d_in[5];
    const float* fb  = (const float*)d_in[6];
    const float* fg  = (const float*)d_in[7];
    const float* fbe = (const float*)d_in[8];
    const float* oW  = (const float*)d_in[9];
    const float* ob  = (const float*)d_in[10];
    const float* og  = (const float*)d_in[11];
    const float* obe = (const float*)d_in[12];
    float* out = (float*)d_out;

    cudaFuncSetAttribute(k2_token,    cudaFuncAttributeMaxDynamicSharedMemorySize, SMB);
    cudaFuncSetAttribute(k3_fuse_out, cudaFuncAttributeMaxDynamicSharedMemorySize, SMB);

    k1_subsum<<<8192, 256>>>(h_pixel);
    k2_token<<<512, 256, SMB>>>(tW, tb, tg, tbe);
    k3_fuse_out<<<1024, 256, SMB>>>(fW, fb, fg, fbe, oW, ob, og, obe, out);
}

// round 10
// speedup vs baseline: 1.1280x; 1.1280x over previous
#include <cuda_runtime.h>
#include <math.h>
#include <stdint.h>

#define EPS  1e-5f
#define HHH  192
#define XSTR 68          // xs row stride (words): A-fragment LDS conflict-free
// smem layout (float offsets)
#define CPO  0                        // params: up to 6 x 64 floats
#define XSO  384                      // xs: 128 x XSTR floats
#define WHIO (XSO + 128 * XSTR)       // 9088: whi2 = 32 rows x 68 float2
#define WLOO (WHIO + 4352)            // 13440: wlo2 = 32 rows x 68 float2
#define SMF  (WLOO + 4352)            // 17792 floats
#define SMB  (SMF * 4)                // 71168 bytes

// Scratch (device globals — allocation-free)
__device__ __align__(16) float g_S[32 * 64 * 64 * 64];        // 3x3 sub-block sums
__device__ __align__(16) float g_tok[2 * 32 * 32 * 32 * 64];  // tokens [p][b][i][j][c]

__device__ __forceinline__ float tf32r(float x) {
    uint32_t u; asm("cvt.rna.tf32.f32 %0, %1;" : "=r"(u) : "f"(x));
    return __uint_as_float(u);
}
__device__ __forceinline__ void mma8(float* d, const uint32_t* a, uint32_t b0, uint32_t b1) {
    asm volatile(
        "mma.sync.aligned.m16n8k8.row.col.f32.tf32.tf32.f32 "
        "{%0,%1,%2,%3}, {%4,%5,%6,%7}, {%8,%9}, {%0,%1,%2,%3};"
        : "+f"(d[0]), "+f"(d[1]), "+f"(d[2]), "+f"(d[3])
        : "r"(a[0]), "r"(a[1]), "r"(a[2]), "r"(a[3]), "r"(b0), "r"(b1));
}
__device__ __forceinline__ float gelu_exact(float v) {
    return 0.5f * v * (1.0f + erff(v * 0.7071067811865476f));
}
#define FU(x) __float_as_uint(x)

// ---------------------------------------------------------------------------
// K1: 3x3 sub-block sums (83% of DRAM roofline — unchanged).
// ---------------------------------------------------------------------------
__global__ void __launch_bounds__(256) k1_subsum(const float* __restrict__ x) {
    int tid = blockIdx.x * blockDim.x + threadIdx.x;
    int c4 = tid & 15;
    int sw = (tid >> 4) & 63;
    int sh = (tid >> 10) & 63;
    int b  = tid >> 16;
    const float4* x4 = (const float4*)x;
    float4 acc = make_float4(0.f, 0.f, 0.f, 0.f);
    int rowbase = (b * HHH + sh * 3) * HHH + sw * 3;
#pragma unroll
    for (int dh = 0; dh < 3; dh++)
#pragma unroll
        for (int dw = 0; dw < 3; dw++) {
            float4 v = x4[(rowbase + dh * HHH + dw) * 16 + c4];
            acc.x += v.x; acc.y += v.y; acc.z += v.z; acc.w += v.w;
        }
    ((float4*)g_S)[tid] = acc;
}

// W[k][n] (64x64) -> paired tf32 hi/lo tiles:
// pair row pr = (k>>3)*4 + (k&3); half = (k>>2)&1 selects .x/.y of the float2
// holding (w[ks*8+q][n], w[ks*8+q+4][n]).
__device__ __forceinline__ void load_wsplit(const float* __restrict__ W, float* sm, int tid) {
    float* whi = sm + WHIO;
    float* wlo = sm + WLOO;
#pragma unroll
    for (int e = 0; e < 4; e++) {
        int idx = e * 256 + tid;
        int k = idx >> 4, n4 = idx & 15;
        float4 wv = ((const float4*)W)[idx];
        int pr = (k >> 3) * 4 + (k & 3);
        int half = (k >> 2) & 1;
        int base = pr * 136 + 8 * n4 + half;
        float h;
        h = tf32r(wv.x); whi[base]     = h; wlo[base]     = tf32r(wv.x - h);
        h = tf32r(wv.y); whi[base + 2] = h; wlo[base + 2] = tf32r(wv.y - h);
        h = tf32r(wv.z); whi[base + 4] = h; wlo[base + 4] = tf32r(wv.z - h);
        h = tf32r(wv.w); whi[base + 6] = h; wlo[base + 6] = tf32r(wv.w - h);
    }
}

// GEMM(128x64 @ 64x64) via mma.sync tf32 3-pass split (pass-major) + LN + GELU.
// Warp w rows [16w,16w+16): v[0]=row 16w+g, v[1]=row 16w+8+g; cols 8j+2q+{0,1}.
__device__ __forceinline__ void gemm_ln_gelu(const float* sm, const float* cp, int tid,
                                             float v[2][16]) {
    int w = tid >> 5, lane = tid & 31, g = lane >> 2, q = lane & 3;
    const float*  xs   = sm + XSO;
    const float2* whi2 = (const float2*)(sm + WHIO);
    const float2* wlo2 = (const float2*)(sm + WLOO);
    float acc[8][4];
#pragma unroll
    for (int j = 0; j < 8; j++) {
        float2 b2 = *(const float2*)(cp + 8 * j + 2 * q);
        acc[j][0] = b2.x; acc[j][1] = b2.y; acc[j][2] = b2.x; acc[j][3] = b2.y;
    }
    int r0 = 16 * w + g;
#pragma unroll
    for (int ks = 0; ks < 8; ks++) {
        int k0 = ks * 8 + q;
        float x0 = xs[r0 * XSTR + k0];
        float x1 = xs[(r0 + 8) * XSTR + k0];
        float x2 = xs[r0 * XSTR + k0 + 4];
        float x3 = xs[(r0 + 8) * XSTR + k0 + 4];
        float h0 = tf32r(x0), h1 = tf32r(x1), h2 = tf32r(x2), h3 = tf32r(x3);
        uint32_t Ahi[4] = { FU(h0), FU(h1), FU(h2), FU(h3) };
        uint32_t Alo[4] = { FU(tf32r(x0 - h0)), FU(tf32r(x1 - h1)),
                            FU(tf32r(x2 - h2)), FU(tf32r(x3 - h3)) };
        const float2* whr = whi2 + (ks * 4 + q) * 68 + g;
        const float2* wlr = wlo2 + (ks * 4 + q) * 68 + g;
        float2 wh[8], wl[8];
#pragma unroll
        for (int j = 0; j < 8; j++) { wh[j] = whr[8 * j]; wl[j] = wlr[8 * j]; }
#pragma unroll
        for (int j = 0; j < 8; j++) mma8(acc[j], Ahi, FU(wh[j].x), FU(wh[j].y));
#pragma unroll
        for (int j = 0; j < 8; j++) mma8(acc[j], Ahi, FU(wl[j].x), FU(wl[j].y));
#pragma unroll
        for (int j = 0; j < 8; j++) mma8(acc[j], Alo, FU(wh[j].x), FU(wh[j].y));
    }
#pragma unroll
    for (int j = 0; j < 8; j++) {
        v[0][2 * j] = acc[j][0]; v[0][2 * j + 1] = acc[j][1];
        v[1][2 * j] = acc[j][2]; v[1][2 * j + 1] = acc[j][3];
    }
#pragma unroll
    for (int t = 0; t < 2; t++) {
        float s = 0.f;
#pragma unroll
        for (int i = 0; i < 16; i++) s += v[t][i];
        s += __shfl_xor_sync(0xffffffffu, s, 1);
        s += __shfl_xor_sync(0xffffffffu, s, 2);
        float mean = s * (1.0f / 64.0f);
        float var = 0.f;
#pragma unroll
        for (int i = 0; i < 16; i++) { float d = v[t][i] - mean; var += d * d; }
        var += __shfl_xor_sync(0xffffffffu, var, 1);
        var += __shfl_xor_sync(0xffffffffu, var, 2);
        float rstd = rsqrtf(var * (1.0f / 64.0f) + EPS);
#pragma unroll
        for (int j = 0; j < 8; j++) {
            float2 gm = *(const float2*)(cp + 64  + 8 * j + 2 * q);
            float2 bt = *(const float2*)(cp + 128 + 8 * j + 2 * q);
            v[t][2 * j]     = gelu_exact((v[t][2 * j]     - mean) * rstd * gm.x + bt.x);
            v[t][2 * j + 1] = gelu_exact((v[t][2 * j + 1] - mean) * rstd * gm.y + bt.y);
        }
    }
}

// ---------------------------------------------------------------------------
// K2: token projection (both paths). 128 rows/CTA, 512 CTAs.
// ---------------------------------------------------------------------------
__global__ void __launch_bounds__(256, 2) k2_token(
    const float* __restrict__ tW, const float* __restrict__ tb,
    const float* __restrict__ tg, const float* __restrict__ tbe)
{
    extern __shared__ __align__(16) float sm[];
    int tid = threadIdx.x;
    if (tid < 64) {
        sm[CPO + tid] = tb[tid]; sm[CPO + 64 + tid] = tg[tid]; sm[CPO + 128 + tid] = tbe[tid];
    }
    load_wsplit(tW, sm, tid);
    float* xs = sm + XSO;
    int R0 = blockIdx.x * 128;
#pragma unroll 2
    for (int e = 0; e < 8; e++) {
        int idx = e * 256 + tid;
        int r = idx >> 4, c4 = idx & 15;
        int R = R0 + r;
        int p = R >> 15, rem = R & 32767;
        int bb = rem >> 10, ii = (rem >> 5) & 31, jj = rem & 31;
        int r0, r1, q0, q1;
        if (p == 0) { r0 = 2 * ii;            r1 = 2 * ii + 1;
                      q0 = 2 * jj;            q1 = 2 * jj + 1; }
        else        { r0 = (2 * ii + 1) & 63; r1 = (2 * ii + 2) & 63;
                      q0 = (2 * jj + 1) & 63; q1 = (2 * jj + 2) & 63; }
        const float4* Sb = (const float4*)g_S + bb * 65536;
        float4 s0 = Sb[(r0 * 64 + q0) * 16 + c4];
        float4 s1 = Sb[(r0 * 64 + q1) * 16 + c4];
        float4 s2 = Sb[(r1 * 64 + q0) * 16 + c4];
        float4 s3 = Sb[(r1 * 64 + q1) * 16 + c4];
        *(float4*)(xs + r * XSTR + 4 * c4) =
            make_float4((s0.x + s1.x + s2.x + s3.x) * (1.0f / 36.0f),
                        (s0.y + s1.y + s2.y + s3.y) * (1.0f / 36.0f),
                        (s0.z + s1.z + s2.z + s3.z) * (1.0f / 36.0f),
                        (s0.w + s1.w + s2.w + s3.w) * (1.0f / 36.0f));
    }
    __syncthreads();
    float v[2][16];
    gemm_ln_gelu(sm, sm + CPO, tid, v);
    int w = tid >> 5, lane = tid & 31, g = lane >> 2, q = lane & 3;
    int R = R0 + 16 * w + g;
#pragma unroll
    for (int j = 0; j < 8; j++) {
        *(float2*)&g_tok[R * 64 + 8 * j + 2 * q]       = make_float2(v[0][2*j], v[0][2*j+1]);
        *(float2*)&g_tok[(R + 8) * 64 + 8 * j + 2 * q] = make_float2(v[1][2*j], v[1][2*j+1]);
    }
}

// ---------------------------------------------------------------------------
// K3: fuse + out layers per unique 3x3 block (128 rows/CTA, 1024 CTAs),
// broadcast each row to its 9 output pixels.
// ---------------------------------------------------------------------------
__global__ void __launch_bounds__(256, 2) k3_fuse_out(
    const float* __restrict__ fW, const float* __restrict__ fb,
    const float* __restrict__ fg, const float* __restrict__ fbe,
    const float* __restrict__ oW, const float* __restrict__ ob,
    const float* __restrict__ og, const float* __restrict__ obe,
    float* __restrict__ out)
{
    extern __shared__ __align__(16) float sm[];
    int tid = threadIdx.x;
    if (tid < 64) {
        sm[CPO + tid]       = fb[tid]; sm[CPO + 64 + tid]  = fg[tid]; sm[CPO + 128 + tid] = fbe[tid];
        sm[CPO + 192 + tid] = ob[tid]; sm[CPO + 256 + tid] = og[tid]; sm[CPO + 320 + tid] = obe[tid];
    }
    load_wsplit(fW, sm, tid);
    float* xs = sm + XSO;
    int R0 = blockIdx.x * 128;
#pragma unroll 2
    for (int e = 0; e < 8; e++) {
        int idx = e * 256 + tid;
        int r = idx >> 4, c4 = idx & 15;
        int R = R0 + r;
        int bb = R >> 12, qh = (R >> 6) & 63, qw = R & 63;
        int ih = qh >> 1, iw = qw >> 1;
        int sh = ((qh + 63) & 63) >> 1, sw_ = ((qw + 63) & 63) >> 1;
        float4 a = ((const float4*)g_tok)[((bb * 32 + ih) * 32 + iw) * 16 + c4];
        float4 s = ((const float4*)g_tok)[524288 + ((bb * 32 + sh) * 32 + sw_) * 16 + c4];
        *(float4*)(xs + r * XSTR + 4 * c4) =
            make_float4(a.x + s.x, a.y + s.y, a.z + s.z, a.w + s.w);
    }
    __syncthreads();
    int w = tid >> 5, lane = tid & 31, g = lane >> 2, q = lane & 3;
    int r0 = 16 * w + g;
    float v[2][16];
    // ---- layer 1: fuse ----
    gemm_ln_gelu(sm, sm + CPO, tid, v);
    __syncthreads();                      // all reads of xs/W done
#pragma unroll
    for (int j = 0; j < 8; j++) {
        *(float2*)&xs[r0 * XSTR + 8 * j + 2 * q]       = make_float2(v[0][2*j], v[0][2*j+1]);
        *(float2*)&xs[(r0 + 8) * XSTR + 8 * j + 2 * q] = make_float2(v[1][2*j], v[1][2*j+1]);
    }
    load_wsplit(oW, sm, tid);
    __syncthreads();
    // ---- layer 2: out ----
    gemm_ln_gelu(sm, sm + CPO + 192, tid, v);
    __syncthreads();                      // all W reads done; reuse W region as ys
    float* ys = sm + WHIO;                // 128 rows x stride 68 = 8704 floats
#pragma unroll
    for (int j = 0; j < 8; j++) {
        *(float2*)&ys[r0 * 68 + 8 * j + 2 * q]       = make_float2(v[0][2*j], v[0][2*j+1]);
        *(float2*)&ys[(r0 + 8) * 68 + 8 * j + 2 * q] = make_float2(v[1][2*j], v[1][2*j+1]);
    }
    __syncthreads();
    // coalesced 3x3 broadcast
    float4* o4 = (float4*)out;
#pragma unroll 2
    for (int e = 0; e < 8; e++) {
        int idx = e * 256 + tid;
        int r = idx >> 4, c4 = idx & 15;
        float4 val = *(float4*)(ys + r * 68 + 4 * c4);
        int R = R0 + r;
        int bb = R >> 12, qh = (R >> 6) & 63, qw = R & 63;
        int base = (bb * 36864 + qh * 3 * HHH + qw * 3) * 16 + c4;
#pragma unroll
        for (int dh = 0; dh < 3; dh++)
#pragma unroll
            for (int dw = 0; dw < 3; dw++)
                o4[base + (dh * HHH + dw) * 16] = val;
    }
}

// ---------------------------------------------------------------------------
extern "C" void kernel_launch(void* const* d_in, const int* in_sizes, int n_in,
                              void* d_out, int out_size) {
    const float* h_pixel = (const float*)d_in[0];
    const float* tW  = (const float*)d_in[1];
    const float* tb  = (const float*)d_in[2];
    const float* tg  = (const float*)d_in[3];
    const float* tbe = (const float*)d_in[4];
    const float* fW  = (const float*)d_in[5];
    const float* fb  = (const float*)d_in[6];
    const float* fg  = (const float*)d_in[7];
    const float* fbe = (const float*)d_in[8];
    const float* oW  = (const float*)d_in[9];
    const float* ob  = (const float*)d_in[10];
    const float* og  = (const float*)d_in[11];
    const float* obe = (const float*)d_in[12];
    float* out = (float*)d_out;

    cudaFuncSetAttribute(k2_token,    cudaFuncAttributeMaxDynamicSharedMemorySize, SMB);
    cudaFuncSetAttribute(k3_fuse_out, cudaFuncAttributeMaxDynamicSharedMemorySize, SMB);

    k1_subsum<<<8192, 256>>>(h_pixel);
    k2_token<<<512, 256, SMB>>>(tW, tb, tg, tbe);
    k3_fuse_out<<<1024, 256, SMB>>>(fW, fb, fg, fbe, oW, ob, og, obe, out);
}

// round 11
// speedup vs baseline: 1.2407x; 1.0999x over previous
#include <cuda_runtime.h>
#include <cuda_bf16.h>
#include <math.h>
#include <stdint.h>

#define EPS  1e-5f
#define HHH  192
// smem layout (u32/float offsets)
#define CPO  0                 // params: up to 6 x 64 floats (384)
#define XHO  384               // X hi: 128 rows x 36 u32 (bf16x2 per k-pair)
#define XLO  4992              // X lo: 128 x 36
#define WHO  9600              // W hi: 16 pair-rows x 68 float2 (2176 u32)
#define WLO  11776             // W lo: same
#define SMF  13952
#define SMB  (SMF * 4)         // 55808 bytes

// Scratch (device globals — allocation-free)
__device__ __align__(16) float g_S[32 * 64 * 64 * 64];        // 3x3 sub-block sums
__device__ __align__(16) float g_tok[2 * 32 * 32 * 32 * 64];  // tokens [p][b][i][j][c]

__device__ __forceinline__ unsigned short f2b(float x) {
    return __bfloat16_as_ushort(__float2bfloat16_rn(x));
}
__device__ __forceinline__ float b2f(unsigned short u) {
    return __uint_as_float(((uint32_t)u) << 16);
}
__device__ __forceinline__ void mma16(float* d, const uint32_t* a, uint32_t b0, uint32_t b1) {
    asm volatile(
        "mma.sync.aligned.m16n8k16.row.col.f32.bf16.bf16.f32 "
        "{%0,%1,%2,%3}, {%4,%5,%6,%7}, {%8,%9}, {%0,%1,%2,%3};"
        : "+f"(d[0]), "+f"(d[1]), "+f"(d[2]), "+f"(d[3])
        : "r"(a[0]), "r"(a[1]), "r"(a[2]), "r"(a[3]), "r"(b0), "r"(b1));
}
__device__ __forceinline__ float gelu_exact(float v) {
    return 0.5f * v * (1.0f + erff(v * 0.7071067811865476f));
}

// ---------------------------------------------------------------------------
// K1: 3x3 sub-block sums (84% of DRAM roofline — unchanged).
// ---------------------------------------------------------------------------
__global__ void __launch_bounds__(256) k1_subsum(const float* __restrict__ x) {
    int tid = blockIdx.x * blockDim.x + threadIdx.x;
    int c4 = tid & 15;
    int sw = (tid >> 4) & 63;
    int sh = (tid >> 10) & 63;
    int b  = tid >> 16;
    const float4* x4 = (const float4*)x;
    float4 acc = make_float4(0.f, 0.f, 0.f, 0.f);
    int rowbase = (b * HHH + sh * 3) * HHH + sw * 3;
#pragma unroll
    for (int dh = 0; dh < 3; dh++)
#pragma unroll
        for (int dw = 0; dw < 3; dw++) {
            float4 v = x4[(rowbase + dh * HHH + dw) * 16 + c4];
            acc.x += v.x; acc.y += v.y; acc.z += v.z; acc.w += v.w;
        }
    ((float4*)g_S)[tid] = acc;
}

// split 4 consecutive k (k=4c4..4c4+3) of row r into packed bf16x2 hi/lo tiles
__device__ __forceinline__ void store_x4(float* sm, int r, int c4, float4 xv) {
    unsigned short h0 = f2b(xv.x), h1 = f2b(xv.y), h2 = f2b(xv.z), h3 = f2b(xv.w);
    uint32_t hh0 = (uint32_t)h0 | ((uint32_t)h1 << 16);
    uint32_t hh1 = (uint32_t)h2 | ((uint32_t)h3 << 16);
    unsigned short l0 = f2b(xv.x - b2f(h0)), l1 = f2b(xv.y - b2f(h1));
    unsigned short l2 = f2b(xv.z - b2f(h2)), l3 = f2b(xv.w - b2f(h3));
    uint32_t ll0 = (uint32_t)l0 | ((uint32_t)l1 << 16);
    uint32_t ll1 = (uint32_t)l2 | ((uint32_t)l3 << 16);
    ((uint2*)(sm + XHO))[r * 18 + c4] = make_uint2(hh0, hh1);
    ((uint2*)(sm + XLO))[r * 18 + c4] = make_uint2(ll0, ll1);
}

// W[k][n] (64x64) -> paired bf16x2 hi/lo tiles.
// pair-row = ks*4 + (pkl&3); float2 component = pkl>>2; bf16 half = k&1,
// where ks=k>>4, pkl=(k&15)>>1.
__device__ __forceinline__ void load_wsplit(const float* __restrict__ W, float* sm, int tid) {
    unsigned short* wh16 = (unsigned short*)(sm + WHO);
    unsigned short* wl16 = (unsigned short*)(sm + WLO);
#pragma unroll
    for (int e = 0; e < 4; e++) {
        int idx = e * 256 + tid;
        int k = idx >> 4, n4 = idx & 15;
        float4 wv = ((const float4*)W)[idx];
        int ks = k >> 4, kk = k & 15, pkl = kk >> 1;
        int row = ks * 4 + (pkl & 3), half = pkl >> 2, par = kk & 1;
        float vv[4] = { wv.x, wv.y, wv.z, wv.w };
#pragma unroll
        for (int jj = 0; jj < 4; jj++) {
            int n = 4 * n4 + jj;
            int u16i = ((((row * 68 + n) * 2 + half) << 1) | par);
            unsigned short hb = f2b(vv[jj]);
            wh16[u16i] = hb;
            wl16[u16i] = f2b(vv[jj] - b2f(hb));
        }
    }
}

// GEMM(128x64 @ 64x64) via mma.sync bf16 m16n8k16, 3-pass split + LN + GELU.
// Warp w rows [16w,16w+16): v[0]=row 16w+g, v[1]=row 16w+8+g; cols 8j+2q+{0,1}.
__device__ __forceinline__ void gemm_ln_gelu(const float* sm, const float* cp, int tid,
                                             float v[2][16]) {
    int w = tid >> 5, lane = tid & 31, g = lane >> 2, q = lane & 3;
    const uint32_t* xh = (const uint32_t*)(sm + XHO);
    const uint32_t* xl = (const uint32_t*)(sm + XLO);
    const uint2* wh2 = (const uint2*)(sm + WHO);
    const uint2* wl2 = (const uint2*)(sm + WLO);
    float acc[8][4];
#pragma unroll
    for (int j = 0; j < 8; j++) {
        float2 b2 = *(const float2*)(cp + 8 * j + 2 * q);
        acc[j][0] = b2.x; acc[j][1] = b2.y; acc[j][2] = b2.x; acc[j][3] = b2.y;
    }
    int r0 = 16 * w;
    const uint32_t* xh0 = xh + (r0 + g) * 36;
    const uint32_t* xh1 = xh + (r0 + 8 + g) * 36;
    const uint32_t* xl0 = xl + (r0 + g) * 36;
    const uint32_t* xl1 = xl + (r0 + 8 + g) * 36;
#pragma unroll
    for (int ks = 0; ks < 4; ks++) {
        int pk = 8 * ks + q;
        uint32_t Ahi[4] = { xh0[pk], xh1[pk], xh0[pk + 4], xh1[pk + 4] };
        uint32_t Alo[4] = { xl0[pk], xl1[pk], xl0[pk + 4], xl1[pk + 4] };
        const uint2* whr = wh2 + (ks * 4 + q) * 68 + g;
        const uint2* wlr = wl2 + (ks * 4 + q) * 68 + g;
        uint2 wh[8], wl[8];
#pragma unroll
        for (int j = 0; j < 8; j++) { wh[j] = whr[8 * j]; wl[j] = wlr[8 * j]; }
#pragma unroll
        for (int j = 0; j < 8; j++) mma16(acc[j], Ahi, wh[j].x, wh[j].y);
#pragma unroll
        for (int j = 0; j < 8; j++) mma16(acc[j], Ahi, wl[j].x, wl[j].y);
#pragma unroll
        for (int j = 0; j < 8; j++) mma16(acc[j], Alo, wh[j].x, wh[j].y);
    }
#pragma unroll
    for (int j = 0; j < 8; j++) {
        v[0][2 * j] = acc[j][0]; v[0][2 * j + 1] = acc[j][1];
        v[1][2 * j] = acc[j][2]; v[1][2 * j + 1] = acc[j][3];
    }
#pragma unroll
    for (int t = 0; t < 2; t++) {
        float s = 0.f;
#pragma unroll
        for (int i = 0; i < 16; i++) s += v[t][i];
        s += __shfl_xor_sync(0xffffffffu, s, 1);
        s += __shfl_xor_sync(0xffffffffu, s, 2);
        float mean = s * (1.0f / 64.0f);
        float var = 0.f;
#pragma unroll
        for (int i = 0; i < 16; i++) { float d = v[t][i] - mean; var += d * d; }
        var += __shfl_xor_sync(0xffffffffu, var, 1);
        var += __shfl_xor_sync(0xffffffffu, var, 2);
        float rstd = rsqrtf(var * (1.0f / 64.0f) + EPS);
#pragma unroll
        for (int j = 0; j < 8; j++) {
            float2 gm = *(const float2*)(cp + 64  + 8 * j + 2 * q);
            float2 bt = *(const float2*)(cp + 128 + 8 * j + 2 * q);
            v[t][2 * j]     = gelu_exact((v[t][2 * j]     - mean) * rstd * gm.x + bt.x);
            v[t][2 * j + 1] = gelu_exact((v[t][2 * j + 1] - mean) * rstd * gm.y + bt.y);
        }
    }
}

// write layer activations back as split bf16x2 (cols 8j+2q form a k-pair)
__device__ __forceinline__ void writeback_split(float* sm, int tid, const float v[2][16]) {
    uint32_t* xh = (uint32_t*)(sm + XHO);
    uint32_t* xl = (uint32_t*)(sm + XLO);
    int w = tid >> 5, lane = tid & 31, g = lane >> 2, q = lane & 3;
#pragma unroll
    for (int t = 0; t < 2; t++) {
        int r = 16 * w + g + 8 * t;
#pragma unroll
        for (int j = 0; j < 8; j++) {
            int pk = 4 * j + q;
            float a = v[t][2 * j], b = v[t][2 * j + 1];
            unsigned short ha = f2b(a), hb = f2b(b);
            xh[r * 36 + pk] = (uint32_t)ha | ((uint32_t)hb << 16);
            unsigned short la = f2b(a - b2f(ha)), lb = f2b(b - b2f(hb));
            xl[r * 36 + pk] = (uint32_t)la | ((uint32_t)lb << 16);
        }
    }
}

// ---------------------------------------------------------------------------
// K2: token projection (both paths). 128 rows/CTA, 512 CTAs.
// ---------------------------------------------------------------------------
__global__ void __launch_bounds__(256, 2) k2_token(
    const float* __restrict__ tW, const float* __restrict__ tb,
    const float* __restrict__ tg, const float* __restrict__ tbe)
{
    extern __shared__ __align__(16) float sm[];
    int tid = threadIdx.x;
    if (tid < 64) {
        sm[CPO + tid] = tb[tid]; sm[CPO + 64 + tid] = tg[tid]; sm[CPO + 128 + tid] = tbe[tid];
    }
    load_wsplit(tW, sm, tid);
    int R0 = blockIdx.x * 128;
#pragma unroll 2
    for (int e = 0; e < 8; e++) {
        int idx = e * 256 + tid;
        int r = idx >> 4, c4 = idx & 15;
        int R = R0 + r;
        int p = R >> 15, rem = R & 32767;
        int bb = rem >> 10, ii = (rem >> 5) & 31, jj = rem & 31;
        int r0, r1, q0, q1;
        if (p == 0) { r0 = 2 * ii;            r1 = 2 * ii + 1;
                      q0 = 2 * jj;            q1 = 2 * jj + 1; }
        else        { r0 = (2 * ii + 1) & 63; r1 = (2 * ii + 2) & 63;
                      q0 = (2 * jj + 1) & 63; q1 = (2 * jj + 2) & 63; }
        const float4* Sb = (const float4*)g_S + bb * 65536;
        float4 s0 = Sb[(r0 * 64 + q0) * 16 + c4];
        float4 s1 = Sb[(r0 * 64 + q1) * 16 + c4];
        float4 s2 = Sb[(r1 * 64 + q0) * 16 + c4];
        float4 s3 = Sb[(r1 * 64 + q1) * 16 + c4];
        store_x4(sm, r, c4,
            make_float4((s0.x + s1.x + s2.x + s3.x) * (1.0f / 36.0f),
                        (s0.y + s1.y + s2.y + s3.y) * (1.0f / 36.0f),
                        (s0.z + s1.z + s2.z + s3.z) * (1.0f / 36.0f),
                        (s0.w + s1.w + s2.w + s3.w) * (1.0f / 36.0f)));
    }
    __syncthreads();
    float v[2][16];
    gemm_ln_gelu(sm, sm + CPO, tid, v);
    int w = tid >> 5, lane = tid & 31, g = lane >> 2, q = lane & 3;
    int R = R0 + 16 * w + g;
#pragma unroll
    for (int j = 0; j < 8; j++) {
        *(float2*)&g_tok[R * 64 + 8 * j + 2 * q]       = make_float2(v[0][2*j], v[0][2*j+1]);
        *(float2*)&g_tok[(R + 8) * 64 + 8 * j + 2 * q] = make_float2(v[1][2*j], v[1][2*j+1]);
    }
}

// ---------------------------------------------------------------------------
// K3: fuse + out layers per unique 3x3 block (128 rows/CTA, 1024 CTAs),
// broadcast each row to its 9 output pixels.
// ---------------------------------------------------------------------------
__global__ void __launch_bounds__(256, 2) k3_fuse_out(
    const float* __restrict__ fW, const float* __restrict__ fb,
    const float* __restrict__ fg, const float* __restrict__ fbe,
    const float* __restrict__ oW, const float* __restrict__ ob,
    const float* __restrict__ og, const float* __restrict__ obe,
    float* __restrict__ out)
{
    extern __shared__ __align__(16) float sm[];
    int tid = threadIdx.x;
    if (tid < 64) {
        sm[CPO + tid]       = fb[tid]; sm[CPO + 64 + tid]  = fg[tid]; sm[CPO + 128 + tid] = fbe[tid];
        sm[CPO + 192 + tid] = ob[tid]; sm[CPO + 256 + tid] = og[tid]; sm[CPO + 320 + tid] = obe[tid];
    }
    load_wsplit(fW, sm, tid);
    int R0 = blockIdx.x * 128;
#pragma unroll 2
    for (int e = 0; e < 8; e++) {
        int idx = e * 256 + tid;
        int r = idx >> 4, c4 = idx & 15;
        int R = R0 + r;
        int bb = R >> 12, qh = (R >> 6) & 63, qw = R & 63;
        int ih = qh >> 1, iw = qw >> 1;
        int sh = ((qh + 63) & 63) >> 1, sw_ = ((qw + 63) & 63) >> 1;
        float4 a = ((const float4*)g_tok)[((bb * 32 + ih) * 32 + iw) * 16 + c4];
        float4 s = ((const float4*)g_tok)[524288 + ((bb * 32 + sh) * 32 + sw_) * 16 + c4];
        store_x4(sm, r, c4, make_float4(a.x + s.x, a.y + s.y, a.z + s.z, a.w + s.w));
    }
    __syncthreads();
    float v[2][16];
    // ---- layer 1: fuse ----
    gemm_ln_gelu(sm, sm + CPO, tid, v);
    __syncthreads();                      // all reads of X/W done
    writeback_split(sm, tid, v);
    load_wsplit(oW, sm, tid);
    __syncthreads();
    // ---- layer 2: out ----
    gemm_ln_gelu(sm, sm + CPO + 192, tid, v);
    __syncthreads();                      // X/W reads done; reuse X region as ys
    float* ys = sm + XHO;                 // 128 rows x stride 68 floats (8704 <= 9216)
    {
        int w = tid >> 5, lane = tid & 31, g = lane >> 2, q = lane & 3;
        int r0 = 16 * w + g;
#pragma unroll
        for (int j = 0; j < 8; j++) {
            *(float2*)&ys[r0 * 68 + 8 * j + 2 * q]       = make_float2(v[0][2*j], v[0][2*j+1]);
            *(float2*)&ys[(r0 + 8) * 68 + 8 * j + 2 * q] = make_float2(v[1][2*j], v[1][2*j+1]);
        }
    }
    __syncthreads();
    // coalesced 3x3 broadcast
    float4* o4 = (float4*)out;
#pragma unroll 2
    for (int e = 0; e < 8; e++) {
        int idx = e * 256 + tid;
        int r = idx >> 4, c4 = idx & 15;
        float4 val = *(float4*)(ys + r * 68 + 4 * c4);
        int R = R0 + r;
        int bb = R >> 12, qh = (R >> 6) & 63, qw = R & 63;
        int base = (bb * 36864 + qh * 3 * HHH + qw * 3) * 16 + c4;
#pragma unroll
        for (int dh = 0; dh < 3; dh++)
#pragma unroll
            for (int dw = 0; dw < 3; dw++)
                o4[base + (dh * HHH + dw) * 16] = val;
    }
}

// ---------------------------------------------------------------------------
extern "C" void kernel_launch(void* const* d_in, const int* in_sizes, int n_in,
                              void* d_out, int out_size) {
    const float* h_pixel = (const float*)d_in[0];
    const float* tW  = (const float*)d_in[1];
    const float* tb  = (const float*)d_in[2];
    const float* tg  = (const float*)d_in[3];
    const float* tbe = (const float*)d_in[4];
    const float* fW  = (const float*)d_in[5];
    const float* fb  = (const float*)d_in[6];
    const float* fg  = (const float*)d_in[7];
    const float* fbe = (const float*)d_in[8];
    const float* oW  = (const float*)d_in[9];
    const float* ob  = (const float*)d_in[10];
    const float* og  = (const float*)d_in[11];
    const float* obe = (const float*)d_in[12];
    float* out = (float*)d_out;

    cudaFuncSetAttribute(k2_token,    cudaFuncAttributeMaxDynamicSharedMemorySize, SMB);
    cudaFuncSetAttribute(k3_fuse_out, cudaFuncAttributeMaxDynamicSharedMemorySize, SMB);

    k1_subsum<<<8192, 256>>>(h_pixel);
    k2_token<<<512, 256, SMB>>>(tW, tb, tg, tbe);
    k3_fuse_out<<<1024, 256, SMB>>>(fW, fb, fg, fbe, oW, ob, og, obe, out);
}

// round 13
// speedup vs baseline: 1.2775x; 1.0296x over previous
#include <cuda_runtime.h>
#include <cuda_bf16.h>
#include <math.h>
#include <stdint.h>

#define EPS  1e-5f
#define HHH  192
// smem layout (u32/float offsets)
#define CPO  0                 // params: up to 6 x 64 floats (384)
#define XHO  384               // X hi: 128 rows x 36 u32 (bf16x2 per k-pair)
#define XLO  4992              // X lo: 128 x 36
#define WHO  9600              // W hi: 16 pair-rows x 68 float2 (2176 u32)
#define WLO  11776             // W lo: same
#define SMF  13952
#define SMB  (SMF * 4)         // 55808 bytes

// Scratch (device globals — allocation-free)
__device__ __align__(16) float g_S[32 * 64 * 64 * 64];        // 3x3 sub-block sums
__device__ __align__(16) float g_tok[2 * 32 * 32 * 32 * 64];  // tokens [p][b][i][j][c]

__device__ __forceinline__ unsigned short f2b(float x) {
    return __bfloat16_as_ushort(__float2bfloat16_rn(x));
}
__device__ __forceinline__ float b2f(unsigned short u) {
    return __uint_as_float(((uint32_t)u) << 16);
}
__device__ __forceinline__ void mma16(float* d, const uint32_t* a, uint32_t b0, uint32_t b1) {
    asm volatile(
        "mma.sync.aligned.m16n8k16.row.col.f32.bf16.bf16.f32 "
        "{%0,%1,%2,%3}, {%4,%5,%6,%7}, {%8,%9}, {%0,%1,%2,%3};"
        : "+f"(d[0]), "+f"(d[1]), "+f"(d[2]), "+f"(d[3])
        : "r"(a[0]), "r"(a[1]), "r"(a[2]), "r"(a[3]), "r"(b0), "r"(b1));
}
__device__ __forceinline__ float gelu_exact(float v) {
    return 0.5f * v * (1.0f + erff(v * 0.7071067811865476f));
}

// ---------------------------------------------------------------------------
// K1: 3x3 sub-block sums (84% of DRAM roofline — unchanged).
// ---------------------------------------------------------------------------
__global__ void __launch_bounds__(256) k1_subsum(const float* __restrict__ x) {
    int tid = blockIdx.x * blockDim.x + threadIdx.x;
    int c4 = tid & 15;
    int sw = (tid >> 4) & 63;
    int sh = (tid >> 10) & 63;
    int b  = tid >> 16;
    const float4* x4 = (const float4*)x;
    float4 acc = make_float4(0.f, 0.f, 0.f, 0.f);
    int rowbase = (b * HHH + sh * 3) * HHH + sw * 3;
#pragma unroll
    for (int dh = 0; dh < 3; dh++)
#pragma unroll
        for (int dw = 0; dw < 3; dw++) {
            float4 v = x4[(rowbase + dh * HHH + dw) * 16 + c4];
            acc.x += v.x; acc.y += v.y; acc.z += v.z; acc.w += v.w;
        }
    ((float4*)g_S)[tid] = acc;
}

// split 4 consecutive k (k=4c4..4c4+3) of row r into packed bf16x2 hi/lo tiles
__device__ __forceinline__ void store_x4(float* sm, int r, int c4, float4 xv) {
    unsigned short h0 = f2b(xv.x), h1 = f2b(xv.y), h2 = f2b(xv.z), h3 = f2b(xv.w);
    uint32_t hh0 = (uint32_t)h0 | ((uint32_t)h1 << 16);
    uint32_t hh1 = (uint32_t)h2 | ((uint32_t)h3 << 16);
    unsigned short l0 = f2b(xv.x - b2f(h0)), l1 = f2b(xv.y - b2f(h1));
    unsigned short l2 = f2b(xv.z - b2f(h2)), l3 = f2b(xv.w - b2f(h3));
    uint32_t ll0 = (uint32_t)l0 | ((uint32_t)l1 << 16);
    uint32_t ll1 = (uint32_t)l2 | ((uint32_t)l3 << 16);
    ((uint2*)(sm + XHO))[r * 18 + c4] = make_uint2(hh0, hh1);
    ((uint2*)(sm + XLO))[r * 18 + c4] = make_uint2(ll0, ll1);
}

// W[k][n] (64x64) -> paired bf16x2 hi/lo tiles.
__device__ __forceinline__ void load_wsplit(const float* __restrict__ W, float* sm, int tid) {
    unsigned short* wh16 = (unsigned short*)(sm + WHO);
    unsigned short* wl16 = (unsigned short*)(sm + WLO);
#pragma unroll
    for (int e = 0; e < 4; e++) {
        int idx = e * 256 + tid;
        int k = idx >> 4, n4 = idx & 15;
        float4 wv = ((const float4*)W)[idx];
        int ks = k >> 4, kk = k & 15, pkl = kk >> 1;
        int row = ks * 4 + (pkl & 3), half = pkl >> 2, par = kk & 1;
        float vv[4] = { wv.x, wv.y, wv.z, wv.w };
#pragma unroll
        for (int jj = 0; jj < 4; jj++) {
            int n = 4 * n4 + jj;
            int u16i = ((((row * 68 + n) * 2 + half) << 1) | par);
            unsigned short hb = f2b(vv[jj]);
            wh16[u16i] = hb;
            wl16[u16i] = f2b(vv[jj] - b2f(hb));
        }
    }
}

// GEMM(128x64 @ 64x64) via mma.sync bf16 m16n8k16, 3-pass split + LN + GELU.
// 4-wide W preload to cap live registers (3 CTAs/SM target).
__device__ __forceinline__ void gemm_ln_gelu(const float* sm, const float* cp, int tid,
                                             float v[2][16]) {
    int w = tid >> 5, lane = tid & 31, g = lane >> 2, q = lane & 3;
    const uint32_t* xh = (const uint32_t*)(sm + XHO);
    const uint32_t* xl = (const uint32_t*)(sm + XLO);
    const uint2* wh2 = (const uint2*)(sm + WHO);
    const uint2* wl2 = (const uint2*)(sm + WLO);
    float acc[8][4];
#pragma unroll
    for (int j = 0; j < 8; j++) {
        float2 b2 = *(const float2*)(cp + 8 * j + 2 * q);
        acc[j][0] = b2.x; acc[j][1] = b2.y; acc[j][2] = b2.x; acc[j][3] = b2.y;
    }
    int r0 = 16 * w;
    const uint32_t* xh0 = xh + (r0 + g) * 36;
    const uint32_t* xh1 = xh + (r0 + 8 + g) * 36;
    const uint32_t* xl0 = xl + (r0 + g) * 36;
    const uint32_t* xl1 = xl + (r0 + 8 + g) * 36;
#pragma unroll
    for (int ks = 0; ks < 4; ks++) {
        int pk = 8 * ks + q;
        uint32_t Ahi[4] = { xh0[pk], xh1[pk], xh0[pk + 4], xh1[pk + 4] };
        uint32_t Alo[4] = { xl0[pk], xl1[pk], xl0[pk + 4], xl1[pk + 4] };
        const uint2* whr = wh2 + (ks * 4 + q) * 68 + g;
        const uint2* wlr = wl2 + (ks * 4 + q) * 68 + g;
#pragma unroll
        for (int jh = 0; jh < 2; jh++) {
            uint2 wh[4], wl[4];
#pragma unroll
            for (int j4 = 0; j4 < 4; j4++) {
                wh[j4] = whr[8 * (4 * jh + j4)];
                wl[j4] = wlr[8 * (4 * jh + j4)];
            }
#pragma unroll
            for (int j4 = 0; j4 < 4; j4++) mma16(acc[4*jh+j4], Ahi, wh[j4].x, wh[j4].y);
#pragma unroll
            for (int j4 = 0; j4 < 4; j4++) mma16(acc[4*jh+j4], Ahi, wl[j4].x, wl[j4].y);
#pragma unroll
            for (int j4 = 0; j4 < 4; j4++) mma16(acc[4*jh+j4], Alo, wh[j4].x, wh[j4].y);
        }
    }
#pragma unroll
    for (int j = 0; j < 8; j++) {
        v[0][2 * j] = acc[j][0]; v[0][2 * j + 1] = acc[j][1];
        v[1][2 * j] = acc[j][2]; v[1][2 * j + 1] = acc[j][3];
    }
#pragma unroll
    for (int t = 0; t < 2; t++) {
        float s = 0.f;
#pragma unroll
        for (int i = 0; i < 16; i++) s += v[t][i];
        s += __shfl_xor_sync(0xffffffffu, s, 1);
        s += __shfl_xor_sync(0xffffffffu, s, 2);
        float mean = s * (1.0f / 64.0f);
        float var = 0.f;
#pragma unroll
        for (int i = 0; i < 16; i++) { float d = v[t][i] - mean; var += d * d; }
        var += __shfl_xor_sync(0xffffffffu, var, 1);
        var += __shfl_xor_sync(0xffffffffu, var, 2);
        float rstd = rsqrtf(var * (1.0f / 64.0f) + EPS);
#pragma unroll
        for (int j = 0; j < 8; j++) {
            float2 gm = *(const float2*)(cp + 64  + 8 * j + 2 * q);
            float2 bt = *(const float2*)(cp + 128 + 8 * j + 2 * q);
            v[t][2 * j]     = gelu_exact((v[t][2 * j]     - mean) * rstd * gm.x + bt.x);
            v[t][2 * j + 1] = gelu_exact((v[t][2 * j + 1] - mean) * rstd * gm.y + bt.y);
        }
    }
}

// write layer activations back as split bf16x2 (cols 8j+2q form a k-pair)
__device__ __forceinline__ void writeback_split(float* sm, int tid, const float v[2][16]) {
    uint32_t* xh = (uint32_t*)(sm + XHO);
    uint32_t* xl = (uint32_t*)(sm + XLO);
    int w = tid >> 5, lane = tid & 31, g = lane >> 2, q = lane & 3;
#pragma unroll
    for (int t = 0; t < 2; t++) {
        int r = 16 * w + g + 8 * t;
#pragma unroll
        for (int j = 0; j < 8; j++) {
            int pk = 4 * j + q;
            float a = v[t][2 * j], b = v[t][2 * j + 1];
            unsigned short ha = f2b(a), hb = f2b(b);
            xh[r * 36 + pk] = (uint32_t)ha | ((uint32_t)hb << 16);
            unsigned short la = f2b(a - b2f(ha)), lb = f2b(b - b2f(hb));
            xl[r * 36 + pk] = (uint32_t)la | ((uint32_t)lb << 16);
        }
    }
}

// ---------------------------------------------------------------------------
// K2: token projection (both paths). 128 rows/CTA, 512 CTAs.
// ---------------------------------------------------------------------------
__global__ void __launch_bounds__(256, 3) k2_token(
    const float* __restrict__ tW, const float* __restrict__ tb,
    const float* __restrict__ tg, const float* __restrict__ tbe)
{
    extern __shared__ __align__(16) float sm[];
    int tid = threadIdx.x;
    if (tid < 64) {
        sm[CPO + tid] = tb[tid]; sm[CPO + 64 + tid] = tg[tid]; sm[CPO + 128 + tid] = tbe[tid];
    }
    load_wsplit(tW, sm, tid);
    int R0 = blockIdx.x * 128;
#pragma unroll 2
    for (int e = 0; e < 8; e++) {
        int idx = e * 256 + tid;
        int r = idx >> 4, c4 = idx & 15;
        int R = R0 + r;
        int p = R >> 15, rem = R & 32767;
        int bb = rem >> 10, ii = (rem >> 5) & 31, jj = rem & 31;
        int r0, r1, q0, q1;
        if (p == 0) { r0 = 2 * ii;            r1 = 2 * ii + 1;
                      q0 = 2 * jj;            q1 = 2 * jj + 1; }
        else        { r0 = (2 * ii + 1) & 63; r1 = (2 * ii + 2) & 63;
                      q0 = (2 * jj + 1) & 63; q1 = (2 * jj + 2) & 63; }
        const float4* Sb = (const float4*)g_S + bb * 65536;
        float4 s0 = Sb[(r0 * 64 + q0) * 16 + c4];
        float4 s1 = Sb[(r0 * 64 + q1) * 16 + c4];
        float4 s2 = Sb[(r1 * 64 + q0) * 16 + c4];
        float4 s3 = Sb[(r1 * 64 + q1) * 16 + c4];
        store_x4(sm, r, c4,
            make_float4((s0.x + s1.x + s2.x + s3.x) * (1.0f / 36.0f),
                        (s0.y + s1.y + s2.y + s3.y) * (1.0f / 36.0f),
                        (s0.z + s1.z + s2.z + s3.z) * (1.0f / 36.0f),
                        (s0.w + s1.w + s2.w + s3.w) * (1.0f / 36.0f)));
    }
    __syncthreads();
    float v[2][16];
    gemm_ln_gelu(sm, sm + CPO, tid, v);
    int w = tid >> 5, lane = tid & 31, g = lane >> 2, q = lane & 3;
    int R = R0 + 16 * w + g;
#pragma unroll
    for (int j = 0; j < 8; j++) {
        *(float2*)&g_tok[R * 64 + 8 * j + 2 * q]       = make_float2(v[0][2*j], v[0][2*j+1]);
        *(float2*)&g_tok[(R + 8) * 64 + 8 * j + 2 * q] = make_float2(v[1][2*j], v[1][2*j+1]);
    }
}

// ---------------------------------------------------------------------------
// K3: fuse + out layers per unique 3x3 block (128 rows/CTA, 1024 CTAs),
// broadcast each row to its 9 output pixels.
// ---------------------------------------------------------------------------
__global__ void __launch_bounds__(256, 3) k3_fuse_out(
    const float* __restrict__ fW, const float* __restrict__ fb,
    const float* __restrict__ fg, const float* __restrict__ fbe,
    const float* __restrict__ oW, const float* __restrict__ ob,
    const float* __restrict__ og, const float* __restrict__ obe,
    float* __restrict__ out)
{
    extern __shared__ __align__(16) float sm[];
    int tid = threadIdx.x;
    if (tid < 64) {
        sm[CPO + tid]       = fb[tid]; sm[CPO + 64 + tid]  = fg[tid]; sm[CPO + 128 + tid] = fbe[tid];
        sm[CPO + 192 + tid] = ob[tid]; sm[CPO + 256 + tid] = og[tid]; sm[CPO + 320 + tid] = obe[tid];
    }
    load_wsplit(fW, sm, tid);
    int R0 = blockIdx.x * 128;
#pragma unroll 2
    for (int e = 0; e < 8; e++) {
        int idx = e * 256 + tid;
        int r = idx >> 4, c4 = idx & 15;
        int R = R0 + r;
        int bb = R >> 12, qh = (R >> 6) & 63, qw = R & 63;
        int ih = qh >> 1, iw = qw >> 1;
        int sh = ((qh + 63) & 63) >> 1, sw_ = ((qw + 63) & 63) >> 1;
        float4 a = ((const float4*)g_tok)[((bb * 32 + ih) * 32 + iw) * 16 + c4];
        float4 s = ((const float4*)g_tok)[524288 + ((bb * 32 + sh) * 32 + sw_) * 16 + c4];
        store_x4(sm, r, c4, make_float4(a.x + s.x, a.y + s.y, a.z + s.z, a.w + s.w));
    }
    __syncthreads();
    float v[2][16];
    // ---- layer 1: fuse ----
    gemm_ln_gelu(sm, sm + CPO, tid, v);
    __syncthreads();                      // all reads of X/W done
    writeback_split(sm, tid, v);
    load_wsplit(oW, sm, tid);
    __syncthreads();
    // ---- layer 2: out ----
    gemm_ln_gelu(sm, sm + CPO + 192, tid, v);
    __syncthreads();                      // X/W reads done; reuse X region as ys
    float* ys = sm + XHO;                 // 128 rows x stride 68 floats
    {
        int w = tid >> 5, lane = tid & 31, g = lane >> 2, q = lane & 3;
        int r0 = 16 * w + g;
#pragma unroll
        for (int j = 0; j < 8; j++) {
            *(float2*)&ys[r0 * 68 + 8 * j + 2 * q]       = make_float2(v[0][2*j], v[0][2*j+1]);
            *(float2*)&ys[(r0 + 8) * 68 + 8 * j + 2 * q] = make_float2(v[1][2*j], v[1][2*j+1]);
        }
    }
    __syncthreads();
    // coalesced 3x3 broadcast
    float4* o4 = (float4*)out;
#pragma unroll 2
    for (int e = 0; e < 8; e++) {
        int idx = e * 256 + tid;
        int r = idx >> 4, c4 = idx & 15;
        float4 val = *(float4*)(ys + r * 68 + 4 * c4);
        int R = R0 + r;
        int bb = R >> 12, qh = (R >> 6) & 63, qw = R & 63;
        int base = (bb * 36864 + qh * 3 * HHH + qw * 3) * 16 + c4;
#pragma unroll
        for (int dh = 0; dh < 3; dh++)
#pragma unroll
            for (int dw = 0; dw < 3; dw++)
                o4[base + (dh * HHH + dw) * 16] = val;
    }
}

// ---------------------------------------------------------------------------
extern "C" void kernel_launch(void* const* d_in, const int* in_sizes, int n_in,
                              void* d_out, int out_size) {
    const float* h_pixel = (const float*)d_in[0];
    const float* tW  = (const float*)d_in[1];
    const float* tb  = (const float*)d_in[2];
    const float* tg  = (const float*)d_in[3];
    const float* tbe = (const float*)d_in[4];
    const float* fW  = (const float*)d_in[5];
    const float* fb  = (const float*)d_in[6];
    const float* fg  = (const float*)d_in[7];
    const float* fbe = (const float*)d_in[8];
    const float* oW  = (const float*)d_in[9];
    const float* ob  = (const float*)d_in[10];
    const float* og  = (const float*)d_in[11];
    const float* obe = (const float*)d_in[12];
    float* out = (float*)d_out;

    cudaFuncSetAttribute(k2_token,    cudaFuncAttributeMaxDynamicSharedMemorySize, SMB);
    cudaFuncSetAttribute(k3_fuse_out, cudaFuncAttributeMaxDynamicSharedMemorySize, SMB);

    k1_subsum<<<8192, 256>>>(h_pixel);
    k2_token<<<512, 256, SMB>>>(tW, tb, tg, tbe);
    k3_fuse_out<<<1024, 256, SMB>>>(fW, fb, fg, fbe, oW, ob, og, obe, out);
}